// round 2
// baseline (speedup 1.0000x reference)
#include <cuda_runtime.h>
#include <math.h>

// ---------------- problem constants ----------------
#define BB    32
#define TTOK  256
#define TT    257          // T_TOK + 1 (class token)
#define CC    1024
#define NHH   16
#define HDD   64
#define LL    12
#define VV    16384
#define MM    (BB * TT)    // 8224 rows
#define C4    (4 * CC)     // 4096
#define LN_EPS 1e-5f
#define ATT_SCALE 0.125f   // 1/sqrt(64)

// ---------------- scratch (device globals; no allocation allowed) ----------------
__device__ float g_x  [(size_t)MM * CC];          //  33.7 MB residual stream
__device__ float g_h  [(size_t)MM * CC];          //  LN output / scratch
__device__ float g_q  [(size_t)MM * CC];
__device__ float g_k  [(size_t)MM * CC];
__device__ float g_v  [(size_t)MM * CC];
__device__ float g_y  [(size_t)MM * CC];
__device__ float g_att[(size_t)BB * NHH * TT * TT];   // 135 MB scores/probs
__device__ float g_mlp[(size_t)MM * C4];              // 135 MB MLP hidden

// ---------------- embedding: x = concat(cls, tok) + pos ----------------
__global__ void __launch_bounds__(256) embed_kernel(
    const float* __restrict__ tok_emb, const float* __restrict__ cls_emb,
    const float* __restrict__ pos_emb, const int* __restrict__ idx_tok,
    const int* __restrict__ idx_cls, float* __restrict__ x)
{
    int bt = blockIdx.x;                 // 0..MM-1
    int b = bt / TT, t = bt % TT;
    const float* src;
    if (t == 0) src = cls_emb + (size_t)idx_cls[b] * CC;
    else        src = tok_emb + (size_t)idx_tok[b * TTOK + (t - 1)] * CC;
    const float4* s4 = (const float4*)src;
    const float4* p4 = (const float4*)(pos_emb + (size_t)t * CC);
    float4*       o4 = (float4*)(x + (size_t)bt * CC);
    int tid = threadIdx.x;               // 256 threads, 1024 floats = 256 float4
    float4 a = s4[tid], p = p4[tid];
    a.x += p.x; a.y += p.y; a.z += p.z; a.w += p.w;
    o4[tid] = a;
}

// ---------------- LayerNorm: one block per row (C=1024, 256 thr x float4) ----------------
__global__ void __launch_bounds__(256) layernorm_kernel(
    const float* __restrict__ x, const float* __restrict__ w,
    const float* __restrict__ b, float* __restrict__ out)
{
    int row = blockIdx.x;
    int tid = threadIdx.x;
    const float4* x4 = (const float4*)(x + (size_t)row * CC);
    float4 v = x4[tid];
    float s  = v.x + v.y + v.z + v.w;
    float ss = v.x * v.x + v.y * v.y + v.z * v.z + v.w * v.w;
    #pragma unroll
    for (int o = 16; o > 0; o >>= 1) {
        s  += __shfl_xor_sync(0xffffffffu, s,  o);
        ss += __shfl_xor_sync(0xffffffffu, ss, o);
    }
    __shared__ float rs[8], rss[8], bc[2];
    int wid = tid >> 5, lane = tid & 31;
    if (lane == 0) { rs[wid] = s; rss[wid] = ss; }
    __syncthreads();
    if (wid == 0) {
        float a  = (lane < 8) ? rs[lane]  : 0.f;
        float a2 = (lane < 8) ? rss[lane] : 0.f;
        #pragma unroll
        for (int o = 4; o > 0; o >>= 1) {
            a  += __shfl_xor_sync(0xffffffffu, a,  o);
            a2 += __shfl_xor_sync(0xffffffffu, a2, o);
        }
        if (lane == 0) { bc[0] = a; bc[1] = a2; }
    }
    __syncthreads();
    float mean = bc[0] * (1.0f / CC);
    float var  = bc[1] * (1.0f / CC) - mean * mean;
    float inv  = rsqrtf(var + LN_EPS);
    const float4* w4 = (const float4*)w;
    const float4* b4 = (const float4*)b;
    float4 wv = w4[tid], bv = b4[tid], o;
    o.x = (v.x - mean) * inv * wv.x + bv.x;
    o.y = (v.y - mean) * inv * wv.y + bv.y;
    o.z = (v.z - mean) * inv * wv.z + bv.z;
    o.w = (v.w - mean) * inv * wv.w + bv.w;
    ((float4*)(out + (size_t)row * CC))[tid] = o;
}

// ---------------- SGEMM v2: C = epilogue(A @ W^T + bias) ----------------
// A: MxK row-major, W: NxK row-major. 128x128 tile, BK=16, 256 threads,
// 8x8 microtile, double-buffered SMEM with register prefetch.
// N % 128 == 0 and K % 16 == 0 for all call sites.
template <bool RES, bool GELU_>
__global__ void __launch_bounds__(256, 2) sgemm_nt(
    const float* __restrict__ A, const float* __restrict__ W,
    const float* __restrict__ bias, const float* __restrict__ res,
    float* __restrict__ C, int M, int N, int K)
{
    __shared__ float As[2][16][128];
    __shared__ float Ws[2][16][128];
    int bm = blockIdx.y * 128;
    int bn = blockIdx.x * 128;
    int tid = threadIdx.x;
    int tx = tid & 15, ty = tid >> 4;

    float acc[8][8];
    #pragma unroll
    for (int i = 0; i < 8; i++)
        #pragma unroll
        for (int j = 0; j < 8; j++) acc[i][j] = 0.f;

    int lrow = tid >> 1;            // 0..127
    int lcol = (tid & 1) * 4;       // 0 or 4; second float4 at lcol+8

    const float* Arow = A + (size_t)(bm + lrow) * K;   // guarded by (bm+lrow<M)
    const float* Wrow = W + (size_t)(bn + lrow) * K;   // always in-bounds

    // ---- preload tile 0 into buffer 0 ----
    {
        float4 a0 = make_float4(0.f,0.f,0.f,0.f), a1 = a0;
        if (bm + lrow < M) {
            a0 = *(const float4*)&Arow[lcol];
            a1 = *(const float4*)&Arow[lcol + 8];
        }
        float4 w0 = *(const float4*)&Wrow[lcol];
        float4 w1 = *(const float4*)&Wrow[lcol + 8];
        As[0][lcol+0][lrow]=a0.x; As[0][lcol+1][lrow]=a0.y;
        As[0][lcol+2][lrow]=a0.z; As[0][lcol+3][lrow]=a0.w;
        As[0][lcol+8][lrow]=a1.x; As[0][lcol+9][lrow]=a1.y;
        As[0][lcol+10][lrow]=a1.z; As[0][lcol+11][lrow]=a1.w;
        Ws[0][lcol+0][lrow]=w0.x; Ws[0][lcol+1][lrow]=w0.y;
        Ws[0][lcol+2][lrow]=w0.z; Ws[0][lcol+3][lrow]=w0.w;
        Ws[0][lcol+8][lrow]=w1.x; Ws[0][lcol+9][lrow]=w1.y;
        Ws[0][lcol+10][lrow]=w1.z; Ws[0][lcol+11][lrow]=w1.w;
    }
    __syncthreads();

    int buf = 0;
    for (int k0 = 0; k0 < K; k0 += 16) {
        // prefetch next K-slab into registers (hides GMEM latency behind FMAs)
        float4 pa0, pa1, pw0, pw1;
        bool has_next = (k0 + 16 < K);
        if (has_next) {
            int kn = k0 + 16;
            pa0 = make_float4(0.f,0.f,0.f,0.f); pa1 = pa0;
            if (bm + lrow < M) {
                pa0 = *(const float4*)&Arow[kn + lcol];
                pa1 = *(const float4*)&Arow[kn + lcol + 8];
            }
            pw0 = *(const float4*)&Wrow[kn + lcol];
            pw1 = *(const float4*)&Wrow[kn + lcol + 8];
        }

        #pragma unroll
        for (int kk = 0; kk < 16; kk++) {
            float ra[8], rb[8];
            float4 a0 = *(float4*)&As[buf][kk][ty * 8];
            float4 a1 = *(float4*)&As[buf][kk][ty * 8 + 4];
            float4 b0 = *(float4*)&Ws[buf][kk][tx * 8];
            float4 b1 = *(float4*)&Ws[buf][kk][tx * 8 + 4];
            ra[0]=a0.x; ra[1]=a0.y; ra[2]=a0.z; ra[3]=a0.w;
            ra[4]=a1.x; ra[5]=a1.y; ra[6]=a1.z; ra[7]=a1.w;
            rb[0]=b0.x; rb[1]=b0.y; rb[2]=b0.z; rb[3]=b0.w;
            rb[4]=b1.x; rb[5]=b1.y; rb[6]=b1.z; rb[7]=b1.w;
            #pragma unroll
            for (int i = 0; i < 8; i++)
                #pragma unroll
                for (int j = 0; j < 8; j++)
                    acc[i][j] = fmaf(ra[i], rb[j], acc[i][j]);
        }

        if (has_next) {
            int nb = buf ^ 1;
            As[nb][lcol+0][lrow]=pa0.x; As[nb][lcol+1][lrow]=pa0.y;
            As[nb][lcol+2][lrow]=pa0.z; As[nb][lcol+3][lrow]=pa0.w;
            As[nb][lcol+8][lrow]=pa1.x; As[nb][lcol+9][lrow]=pa1.y;
            As[nb][lcol+10][lrow]=pa1.z; As[nb][lcol+11][lrow]=pa1.w;
            Ws[nb][lcol+0][lrow]=pw0.x; Ws[nb][lcol+1][lrow]=pw0.y;
            Ws[nb][lcol+2][lrow]=pw0.z; Ws[nb][lcol+3][lrow]=pw0.w;
            Ws[nb][lcol+8][lrow]=pw1.x; Ws[nb][lcol+9][lrow]=pw1.y;
            Ws[nb][lcol+10][lrow]=pw1.z; Ws[nb][lcol+11][lrow]=pw1.w;
            __syncthreads();
            buf = nb;
        }
    }

    #pragma unroll
    for (int i = 0; i < 8; i++) {
        int gm = bm + ty * 8 + i;
        if (gm >= M) continue;
        #pragma unroll
        for (int j = 0; j < 8; j++) {
            int gn = bn + tx * 8 + j;
            float v = acc[i][j];
            if (bias) v += bias[gn];
            if (GELU_) v = 0.5f * v * (1.f + erff(v * 0.70710678118f));
            if (RES) v += res[(size_t)gm * N + gn];
            C[(size_t)gm * N + gn] = v;
        }
    }
}

// ---------------- attention scores: s[b,h,i,j] = q.k * scale (lower tri only) ----------------
__global__ void __launch_bounds__(256) attn_scores_kernel(
    const float* __restrict__ q, const float* __restrict__ k, float* __restrict__ att)
{
    int jt = blockIdx.x, it = blockIdx.y;
    if (jt > it) return;                     // tile fully above diagonal
    int bh = blockIdx.z;
    int b = bh / NHH, h = bh % NHH;
    __shared__ float Qs[32][65];
    __shared__ float Ks[32][65];
    int tid = threadIdx.x;

    #pragma unroll
    for (int rep = 0; rep < 2; rep++) {
        int f = tid + rep * 256;             // 0..511
        int row = f >> 4;                    // 0..31
        int c4  = (f & 15) * 4;              // 0..60
        {
            int i = it * 32 + row;
            float4 v = make_float4(0.f, 0.f, 0.f, 0.f);
            if (i < TT) v = *(const float4*)&q[(((size_t)b * TT + i) * NHH + h) * HDD + c4];
            Qs[row][c4+0]=v.x; Qs[row][c4+1]=v.y; Qs[row][c4+2]=v.z; Qs[row][c4+3]=v.w;
        }
        {
            int j = jt * 32 + row;
            float4 v = make_float4(0.f, 0.f, 0.f, 0.f);
            if (j < TT) v = *(const float4*)&k[(((size_t)b * TT + j) * NHH + h) * HDD + c4];
            Ks[row][c4+0]=v.x; Ks[row][c4+1]=v.y; Ks[row][c4+2]=v.z; Ks[row][c4+3]=v.w;
        }
    }
    __syncthreads();

    int il = tid >> 3;                       // 0..31
    int jb = (tid & 7) * 4;                  // 0..28
    float a0 = 0.f, a1 = 0.f, a2 = 0.f, a3 = 0.f;
    #pragma unroll
    for (int kk = 0; kk < 64; kk++) {
        float qv = Qs[il][kk];
        a0 = fmaf(qv, Ks[jb + 0][kk], a0);
        a1 = fmaf(qv, Ks[jb + 1][kk], a1);
        a2 = fmaf(qv, Ks[jb + 2][kk], a2);
        a3 = fmaf(qv, Ks[jb + 3][kk], a3);
    }
    int i = it * 32 + il;
    if (i < TT) {
        size_t base = ((size_t)bh * TT + i) * TT;
        float r[4] = {a0, a1, a2, a3};
        #pragma unroll
        for (int u = 0; u < 4; u++) {
            int j = jt * 32 + jb + u;
            if (j < TT && j <= i) att[base + j] = r[u] * ATT_SCALE;
        }
    }
}

// ---------------- causal softmax: one warp per (b,h,i) row; zeros beyond i ----------------
__global__ void __launch_bounds__(128) softmax_kernel(float* __restrict__ att)
{
    int row = blockIdx.x * 4 + (threadIdx.x >> 5);
    if (row >= BB * NHH * TT) return;
    int lane = threadIdx.x & 31;
    int i = row % TT;
    float* p = att + (size_t)row * TT;
    int len = i + 1;
    float m = -3.4e38f;
    for (int j = lane; j < len; j += 32) m = fmaxf(m, p[j]);
    #pragma unroll
    for (int o = 16; o > 0; o >>= 1) m = fmaxf(m, __shfl_xor_sync(0xffffffffu, m, o));
    float s = 0.f;
    for (int j = lane; j < len; j += 32) { float e = expf(p[j] - m); p[j] = e; s += e; }
    #pragma unroll
    for (int o = 16; o > 0; o >>= 1) s += __shfl_xor_sync(0xffffffffu, s, o);
    float inv = 1.f / s;
    for (int j = lane; j < TT; j += 32) p[j] = (j < len) ? p[j] * inv : 0.f;
}

// ---------------- AV: y[b,i,h,d] = sum_j att[b,h,i,j] * v[b,j,h,d] ----------------
__global__ void __launch_bounds__(256) attn_av_kernel(
    const float* __restrict__ att, const float* __restrict__ v, float* __restrict__ y)
{
    int it = blockIdx.x, dt = blockIdx.y, bh = blockIdx.z;
    int b = bh / NHH, h = bh % NHH;
    __shared__ float As[32][33];
    __shared__ float Vs[32][33];
    int tid = threadIdx.x;
    int il = tid >> 3;                       // 0..31
    int db = (tid & 7) * 4;                  // 0..28
    float acc0 = 0.f, acc1 = 0.f, acc2 = 0.f, acc3 = 0.f;

    for (int j0 = 0; j0 < TT; j0 += 32) {
        {
            int r  = tid >> 3;
            int cb = (tid & 7) * 4;
            int i  = it * 32 + r;
            #pragma unroll
            for (int u = 0; u < 4; u++) {
                int j = j0 + cb + u;
                As[r][cb + u] = (i < TT && j < TT) ? att[((size_t)bh * TT + i) * TT + j] : 0.f;
            }
            int jr = j0 + r;
            float4 vv = make_float4(0.f, 0.f, 0.f, 0.f);
            if (jr < TT)
                vv = *(const float4*)&v[(((size_t)b * TT + jr) * NHH + h) * HDD + dt * 32 + cb];
            Vs[r][cb+0]=vv.x; Vs[r][cb+1]=vv.y; Vs[r][cb+2]=vv.z; Vs[r][cb+3]=vv.w;
        }
        __syncthreads();
        #pragma unroll
        for (int jj = 0; jj < 32; jj++) {
            float a = As[il][jj];
            acc0 = fmaf(a, Vs[jj][db + 0], acc0);
            acc1 = fmaf(a, Vs[jj][db + 1], acc1);
            acc2 = fmaf(a, Vs[jj][db + 2], acc2);
            acc3 = fmaf(a, Vs[jj][db + 3], acc3);
        }
        __syncthreads();
    }
    int i = it * 32 + il;
    if (i < TT) {
        size_t base = (((size_t)b * TT + i) * NHH + h) * HDD + dt * 32 + db;
        float4 o = make_float4(acc0, acc1, acc2, acc3);
        *(float4*)&y[base] = o;
    }
}

// ---------------- host orchestration ----------------
extern "C" void kernel_launch(void* const* d_in, const int* in_sizes, int n_in,
                              void* d_out, int out_size)
{
    const float* tok_emb = (const float*)d_in[0];
    const float* cls_emb = (const float*)d_in[1];
    const float* pos_emb = (const float*)d_in[2];
    const float* ln1_w   = (const float*)d_in[3];
    const float* ln1_b   = (const float*)d_in[4];
    const float* Wq      = (const float*)d_in[5];
    const float* bq      = (const float*)d_in[6];
    const float* Wk      = (const float*)d_in[7];
    const float* bk      = (const float*)d_in[8];
    const float* Wv      = (const float*)d_in[9];
    const float* bv      = (const float*)d_in[10];
    const float* Wo      = (const float*)d_in[11];
    const float* bo      = (const float*)d_in[12];
    const float* ln2_w   = (const float*)d_in[13];
    const float* ln2_b   = (const float*)d_in[14];
    const float* W1      = (const float*)d_in[15];
    const float* b1      = (const float*)d_in[16];
    const float* W2      = (const float*)d_in[17];
    const float* b2      = (const float*)d_in[18];
    const float* lnf_w   = (const float*)d_in[19];
    const float* lnf_b   = (const float*)d_in[20];
    const int* idx_tok   = (const int*)d_in[21];
    const int* idx_cls   = (const int*)d_in[22];
    float* out = (float*)d_out;

    float *X, *H, *Q, *K, *V, *Y, *ATT, *MLP;
    cudaGetSymbolAddress((void**)&X,   g_x);
    cudaGetSymbolAddress((void**)&H,   g_h);
    cudaGetSymbolAddress((void**)&Q,   g_q);
    cudaGetSymbolAddress((void**)&K,   g_k);
    cudaGetSymbolAddress((void**)&V,   g_v);
    cudaGetSymbolAddress((void**)&Y,   g_y);
    cudaGetSymbolAddress((void**)&ATT, g_att);
    cudaGetSymbolAddress((void**)&MLP, g_mlp);

    embed_kernel<<<MM, 256>>>(tok_emb, cls_emb, pos_emb, idx_tok, idx_cls, X);

    dim3 gridProj(CC / 128, (MM + 127) / 128);         // 8  x 65
    dim3 gridMlp1(C4 / 128, (MM + 127) / 128);         // 32 x 65
    dim3 gridMlp2(CC / 128, (MM + 127) / 128);
    dim3 gridLogit(VV / 128, (MM + 127) / 128);        // 128 x 65
    dim3 gridScore(9, 9, BB * NHH);
    dim3 gridAV(9, 2, BB * NHH);
    int smRows = (BB * NHH * TT + 3) / 4;

    for (int l = 0; l < LL; l++) {
        const float* l1w = ln1_w + (size_t)l * CC;
        const float* l1b = ln1_b + (size_t)l * CC;
        const float* wq  = Wq + (size_t)l * CC * CC;
        const float* wk  = Wk + (size_t)l * CC * CC;
        const float* wv  = Wv + (size_t)l * CC * CC;
        const float* wo  = Wo + (size_t)l * CC * CC;
        const float* bql = bq + (size_t)l * CC;
        const float* bkl = bk + (size_t)l * CC;
        const float* bvl = bv + (size_t)l * CC;
        const float* bol = bo + (size_t)l * CC;
        const float* l2w = ln2_w + (size_t)l * CC;
        const float* l2b = ln2_b + (size_t)l * CC;
        const float* w1  = W1 + (size_t)l * C4 * CC;
        const float* b1l = b1 + (size_t)l * C4;
        const float* w2  = W2 + (size_t)l * CC * C4;
        const float* b2l = b2 + (size_t)l * CC;

        layernorm_kernel<<<MM, 256>>>(X, l1w, l1b, H);

        sgemm_nt<false, false><<<gridProj, 256>>>(H, wq, bql, nullptr, Q, MM, CC, CC);
        sgemm_nt<false, false><<<gridProj, 256>>>(H, wk, bkl, nullptr, K, MM, CC, CC);
        sgemm_nt<false, false><<<gridProj, 256>>>(H, wv, bvl, nullptr, V, MM, CC, CC);

        attn_scores_kernel<<<gridScore, 256>>>(Q, K, ATT);
        softmax_kernel<<<smRows, 128>>>(ATT);
        attn_av_kernel<<<gridAV, 256>>>(ATT, V, Y);

        // x = x + y @ Wo^T + bo
        sgemm_nt<true, false><<<gridProj, 256>>>(Y, wo, bol, X, X, MM, CC, CC);

        layernorm_kernel<<<MM, 256>>>(X, l2w, l2b, H);
        // mlp hidden = gelu(h @ W1^T + b1)
        sgemm_nt<false, true><<<gridMlp1, 256>>>(H, w1, b1l, nullptr, MLP, MM, C4, CC);
        // x = x + mlp @ W2^T + b2
        sgemm_nt<true, false><<<gridMlp2, 256>>>(MLP, w2, b2l, X, X, MM, CC, C4);
    }

    layernorm_kernel<<<MM, 256>>>(X, lnf_w, lnf_b, H);
    // logits = h @ tok_emb^T   (no bias, no residual)
    sgemm_nt<false, false><<<gridLogit, 256>>>(H, tok_emb, nullptr, nullptr, out, MM, VV, CC);
}

// round 3
// speedup vs baseline: 2.0007x; 2.0007x over previous
#include <cuda_runtime.h>
#include <math.h>
#include <stdint.h>

// ---------------- problem constants ----------------
#define BB    32
#define TTOK  256
#define TT    257          // T_TOK + 1 (class token)
#define CC    1024
#define NHH   16
#define HDD   64
#define LL    12
#define VV    16384
#define MM    (BB * TT)    // 8224 rows
#define C4    (4 * CC)     // 4096
#define LN_EPS 1e-5f
#define ATT_SCALE 0.125f   // 1/sqrt(64)

// ---------------- scratch (device globals; no allocation allowed) ----------------
__device__ float g_x  [(size_t)MM * CC];
__device__ float g_h  [(size_t)MM * CC];
__device__ float g_q  [(size_t)MM * CC];
__device__ float g_k  [(size_t)MM * CC];
__device__ float g_v  [(size_t)MM * CC];
__device__ float g_y  [(size_t)MM * CC];
__device__ float g_att[(size_t)BB * NHH * TT * TT];
__device__ float g_mlp[(size_t)MM * C4];

// ---------------- tf32 helpers ----------------
__device__ __forceinline__ uint32_t f2tf32(float f) {
    uint32_t u;
    asm("cvt.rna.tf32.f32 %0, %1;" : "=r"(u) : "f"(f));
    return u;
}

__device__ __forceinline__ void mma_tf32(float* c, const uint32_t* a,
                                         uint32_t b0, uint32_t b1) {
    asm volatile(
        "mma.sync.aligned.m16n8k8.row.col.f32.tf32.tf32.f32 "
        "{%0,%1,%2,%3}, {%4,%5,%6,%7}, {%8,%9}, {%0,%1,%2,%3};\n"
        : "+f"(c[0]), "+f"(c[1]), "+f"(c[2]), "+f"(c[3])
        : "r"(a[0]), "r"(a[1]), "r"(a[2]), "r"(a[3]), "r"(b0), "r"(b1));
}

// ---------------- embedding ----------------
__global__ void __launch_bounds__(256) embed_kernel(
    const float* __restrict__ tok_emb, const float* __restrict__ cls_emb,
    const float* __restrict__ pos_emb, const int* __restrict__ idx_tok,
    const int* __restrict__ idx_cls, float* __restrict__ x)
{
    int bt = blockIdx.x;
    int b = bt / TT, t = bt % TT;
    const float* src;
    if (t == 0) src = cls_emb + (size_t)idx_cls[b] * CC;
    else        src = tok_emb + (size_t)idx_tok[b * TTOK + (t - 1)] * CC;
    const float4* s4 = (const float4*)src;
    const float4* p4 = (const float4*)(pos_emb + (size_t)t * CC);
    float4*       o4 = (float4*)(x + (size_t)bt * CC);
    int tid = threadIdx.x;
    float4 a = s4[tid], p = p4[tid];
    a.x += p.x; a.y += p.y; a.z += p.z; a.w += p.w;
    o4[tid] = a;
}

// ---------------- LayerNorm ----------------
__global__ void __launch_bounds__(256) layernorm_kernel(
    const float* __restrict__ x, const float* __restrict__ w,
    const float* __restrict__ b, float* __restrict__ out)
{
    int row = blockIdx.x;
    int tid = threadIdx.x;
    const float4* x4 = (const float4*)(x + (size_t)row * CC);
    float4 v = x4[tid];
    float s  = v.x + v.y + v.z + v.w;
    float ss = v.x * v.x + v.y * v.y + v.z * v.z + v.w * v.w;
    #pragma unroll
    for (int o = 16; o > 0; o >>= 1) {
        s  += __shfl_xor_sync(0xffffffffu, s,  o);
        ss += __shfl_xor_sync(0xffffffffu, ss, o);
    }
    __shared__ float rs[8], rss[8], bc[2];
    int wid = tid >> 5, lane = tid & 31;
    if (lane == 0) { rs[wid] = s; rss[wid] = ss; }
    __syncthreads();
    if (wid == 0) {
        float a  = (lane < 8) ? rs[lane]  : 0.f;
        float a2 = (lane < 8) ? rss[lane] : 0.f;
        #pragma unroll
        for (int o = 4; o > 0; o >>= 1) {
            a  += __shfl_xor_sync(0xffffffffu, a,  o);
            a2 += __shfl_xor_sync(0xffffffffu, a2, o);
        }
        if (lane == 0) { bc[0] = a; bc[1] = a2; }
    }
    __syncthreads();
    float mean = bc[0] * (1.0f / CC);
    float var  = bc[1] * (1.0f / CC) - mean * mean;
    float inv  = rsqrtf(var + LN_EPS);
    const float4* w4 = (const float4*)w;
    const float4* b4 = (const float4*)b;
    float4 wv = w4[tid], bv = b4[tid], o;
    o.x = (v.x - mean) * inv * wv.x + bv.x;
    o.y = (v.y - mean) * inv * wv.y + bv.y;
    o.z = (v.z - mean) * inv * wv.z + bv.z;
    o.w = (v.w - mean) * inv * wv.w + bv.w;
    ((float4*)(out + (size_t)row * CC))[tid] = o;
}

// ---------------- TF32 tensor-core GEMM: C = epi(A @ W^T + bias) ----------------
// A: MxK row-major fp32, W: NxK row-major fp32. Block tile 128x128, BK=16.
// 8 warps, each 32x64 (2x8 grid of m16n8k8). Inputs cvt.rna -> tf32, fp32 accum.
// SMEM stride 20 words => fragment LDS is bank-conflict-free.
// Requirements (all call sites satisfy): N % 128 == 0, K % 16 == 0.
#define SM_STRIDE 20
template <bool RES, bool GELU_>
__global__ void __launch_bounds__(256, 2) tgemm_nt(
    const float* __restrict__ A, const float* __restrict__ W,
    const float* __restrict__ bias, const float* __restrict__ res,
    float* __restrict__ C, int M, int N, int K)
{
    __shared__ uint32_t As[2][128 * SM_STRIDE];
    __shared__ uint32_t Bs[2][128 * SM_STRIDE];

    int bm = blockIdx.y * 128;
    int bn = blockIdx.x * 128;
    int tid = threadIdx.x;
    int lane = tid & 31;
    int wid  = tid >> 5;
    int g  = lane >> 2;          // groupID 0..7
    int t4 = lane & 3;           // 0..3
    int wm = (wid & 3) * 32;     // warp m offset in tile
    int wn = (wid >> 2) * 64;    // warp n offset in tile

    // loader mapping: 2048 floats per matrix per tile, 8 per thread
    int lrow = tid >> 1;          // 0..127
    int lcol = (tid & 1) * 8;     // 0 or 8

    const float* Arow = A + (size_t)(bm + lrow) * K;
    const float* Wrow = W + (size_t)(bn + lrow) * K;
    bool a_ok = (bm + lrow) < M;

    float acc[2][8][4];
    #pragma unroll
    for (int im = 0; im < 2; im++)
        #pragma unroll
        for (int in_ = 0; in_ < 8; in_++)
            #pragma unroll
            for (int r = 0; r < 4; r++) acc[im][in_][r] = 0.f;

    // ---- preload tile 0 ----
    {
        float4 a0 = make_float4(0.f,0.f,0.f,0.f), a1 = a0;
        if (a_ok) {
            a0 = *(const float4*)&Arow[lcol];
            a1 = *(const float4*)&Arow[lcol + 4];
        }
        float4 w0 = *(const float4*)&Wrow[lcol];
        float4 w1 = *(const float4*)&Wrow[lcol + 4];
        uint4 ua0 = make_uint4(f2tf32(a0.x), f2tf32(a0.y), f2tf32(a0.z), f2tf32(a0.w));
        uint4 ua1 = make_uint4(f2tf32(a1.x), f2tf32(a1.y), f2tf32(a1.z), f2tf32(a1.w));
        uint4 uw0 = make_uint4(f2tf32(w0.x), f2tf32(w0.y), f2tf32(w0.z), f2tf32(w0.w));
        uint4 uw1 = make_uint4(f2tf32(w1.x), f2tf32(w1.y), f2tf32(w1.z), f2tf32(w1.w));
        *(uint4*)&As[0][lrow * SM_STRIDE + lcol]     = ua0;
        *(uint4*)&As[0][lrow * SM_STRIDE + lcol + 4] = ua1;
        *(uint4*)&Bs[0][lrow * SM_STRIDE + lcol]     = uw0;
        *(uint4*)&Bs[0][lrow * SM_STRIDE + lcol + 4] = uw1;
    }
    __syncthreads();

    int buf = 0;
    for (int k0 = 0; k0 < K; k0 += 16) {
        // register prefetch of next K-slab
        float4 pa0, pa1, pw0, pw1;
        bool has_next = (k0 + 16 < K);
        if (has_next) {
            int kn = k0 + 16;
            pa0 = make_float4(0.f,0.f,0.f,0.f); pa1 = pa0;
            if (a_ok) {
                pa0 = *(const float4*)&Arow[kn + lcol];
                pa1 = *(const float4*)&Arow[kn + lcol + 4];
            }
            pw0 = *(const float4*)&Wrow[kn + lcol];
            pw1 = *(const float4*)&Wrow[kn + lcol + 4];
        }

        // ---- compute on current buffer: 2 k-steps of 8 ----
        #pragma unroll
        for (int ks = 0; ks < 2; ks++) {
            int kb = ks * 8;
            uint32_t af[2][4];
            #pragma unroll
            for (int im = 0; im < 2; im++) {
                const uint32_t* Ab = &As[buf][(wm + im * 16) * SM_STRIDE + kb];
                af[im][0] = Ab[ g      * SM_STRIDE + t4];
                af[im][1] = Ab[(g + 8) * SM_STRIDE + t4];
                af[im][2] = Ab[ g      * SM_STRIDE + t4 + 4];
                af[im][3] = Ab[(g + 8) * SM_STRIDE + t4 + 4];
            }
            #pragma unroll
            for (int in_ = 0; in_ < 8; in_++) {
                const uint32_t* Bb = &Bs[buf][(wn + in_ * 8 + g) * SM_STRIDE + kb];
                uint32_t b0 = Bb[t4];
                uint32_t b1 = Bb[t4 + 4];
                mma_tf32(acc[0][in_], af[0], b0, b1);
                mma_tf32(acc[1][in_], af[1], b0, b1);
            }
        }

        if (has_next) {
            int nb = buf ^ 1;
            uint4 ua0 = make_uint4(f2tf32(pa0.x), f2tf32(pa0.y), f2tf32(pa0.z), f2tf32(pa0.w));
            uint4 ua1 = make_uint4(f2tf32(pa1.x), f2tf32(pa1.y), f2tf32(pa1.z), f2tf32(pa1.w));
            uint4 uw0 = make_uint4(f2tf32(pw0.x), f2tf32(pw0.y), f2tf32(pw0.z), f2tf32(pw0.w));
            uint4 uw1 = make_uint4(f2tf32(pw1.x), f2tf32(pw1.y), f2tf32(pw1.z), f2tf32(pw1.w));
            *(uint4*)&As[nb][lrow * SM_STRIDE + lcol]     = ua0;
            *(uint4*)&As[nb][lrow * SM_STRIDE + lcol + 4] = ua1;
            *(uint4*)&Bs[nb][lrow * SM_STRIDE + lcol]     = uw0;
            *(uint4*)&Bs[nb][lrow * SM_STRIDE + lcol + 4] = uw1;
            __syncthreads();
            buf = nb;
        }
    }

    // ---- epilogue: c0,c1 -> row g ; c2,c3 -> row g+8 ; cols 2*t4, 2*t4+1 ----
    #pragma unroll
    for (int im = 0; im < 2; im++) {
        int r0 = bm + wm + im * 16 + g;
        #pragma unroll
        for (int in_ = 0; in_ < 8; in_++) {
            int col = bn + wn + in_ * 8 + t4 * 2;
            float bx = 0.f, by = 0.f;
            if (bias) { bx = bias[col]; by = bias[col + 1]; }
            #pragma unroll
            for (int half = 0; half < 2; half++) {
                int row = r0 + half * 8;
                if (row >= M) continue;
                float vx = acc[im][in_][half * 2 + 0] + bx;
                float vy = acc[im][in_][half * 2 + 1] + by;
                if (GELU_) {
                    vx = 0.5f * vx * (1.f + erff(vx * 0.70710678118f));
                    vy = 0.5f * vy * (1.f + erff(vy * 0.70710678118f));
                }
                if (RES) {
                    float2 rv = *(const float2*)&res[(size_t)row * N + col];
                    vx += rv.x; vy += rv.y;
                }
                float2 o = make_float2(vx, vy);
                *(float2*)&C[(size_t)row * N + col] = o;
            }
        }
    }
}

// ---------------- attention scores (fp32) ----------------
__global__ void __launch_bounds__(256) attn_scores_kernel(
    const float* __restrict__ q, const float* __restrict__ k, float* __restrict__ att)
{
    int jt = blockIdx.x, it = blockIdx.y;
    if (jt > it) return;
    int bh = blockIdx.z;
    int b = bh / NHH, h = bh % NHH;
    __shared__ float Qs[32][65];
    __shared__ float Ks[32][65];
    int tid = threadIdx.x;

    #pragma unroll
    for (int rep = 0; rep < 2; rep++) {
        int f = tid + rep * 256;
        int row = f >> 4;
        int c4  = (f & 15) * 4;
        {
            int i = it * 32 + row;
            float4 v = make_float4(0.f, 0.f, 0.f, 0.f);
            if (i < TT) v = *(const float4*)&q[(((size_t)b * TT + i) * NHH + h) * HDD + c4];
            Qs[row][c4+0]=v.x; Qs[row][c4+1]=v.y; Qs[row][c4+2]=v.z; Qs[row][c4+3]=v.w;
        }
        {
            int j = jt * 32 + row;
            float4 v = make_float4(0.f, 0.f, 0.f, 0.f);
            if (j < TT) v = *(const float4*)&k[(((size_t)b * TT + j) * NHH + h) * HDD + c4];
            Ks[row][c4+0]=v.x; Ks[row][c4+1]=v.y; Ks[row][c4+2]=v.z; Ks[row][c4+3]=v.w;
        }
    }
    __syncthreads();

    int il = tid >> 3;
    int jb = (tid & 7) * 4;
    float a0 = 0.f, a1 = 0.f, a2 = 0.f, a3 = 0.f;
    #pragma unroll
    for (int kk = 0; kk < 64; kk++) {
        float qv = Qs[il][kk];
        a0 = fmaf(qv, Ks[jb + 0][kk], a0);
        a1 = fmaf(qv, Ks[jb + 1][kk], a1);
        a2 = fmaf(qv, Ks[jb + 2][kk], a2);
        a3 = fmaf(qv, Ks[jb + 3][kk], a3);
    }
    int i = it * 32 + il;
    if (i < TT) {
        size_t base = ((size_t)bh * TT + i) * TT;
        float r[4] = {a0, a1, a2, a3};
        #pragma unroll
        for (int u = 0; u < 4; u++) {
            int j = jt * 32 + jb + u;
            if (j < TT && j <= i) att[base + j] = r[u] * ATT_SCALE;
        }
    }
}

// ---------------- causal softmax ----------------
__global__ void __launch_bounds__(128) softmax_kernel(float* __restrict__ att)
{
    int row = blockIdx.x * 4 + (threadIdx.x >> 5);
    if (row >= BB * NHH * TT) return;
    int lane = threadIdx.x & 31;
    int i = row % TT;
    float* p = att + (size_t)row * TT;
    int len = i + 1;
    float m = -3.4e38f;
    for (int j = lane; j < len; j += 32) m = fmaxf(m, p[j]);
    #pragma unroll
    for (int o = 16; o > 0; o >>= 1) m = fmaxf(m, __shfl_xor_sync(0xffffffffu, m, o));
    float s = 0.f;
    for (int j = lane; j < len; j += 32) { float e = expf(p[j] - m); p[j] = e; s += e; }
    #pragma unroll
    for (int o = 16; o > 0; o >>= 1) s += __shfl_xor_sync(0xffffffffu, s, o);
    float inv = 1.f / s;
    for (int j = lane; j < TT; j += 32) p[j] = (j < len) ? p[j] * inv : 0.f;
}

// ---------------- AV (fp32) ----------------
__global__ void __launch_bounds__(256) attn_av_kernel(
    const float* __restrict__ att, const float* __restrict__ v, float* __restrict__ y)
{
    int it = blockIdx.x, dt = blockIdx.y, bh = blockIdx.z;
    int b = bh / NHH, h = bh % NHH;
    __shared__ float As[32][33];
    __shared__ float Vs[32][33];
    int tid = threadIdx.x;
    int il = tid >> 3;
    int db = (tid & 7) * 4;
    float acc0 = 0.f, acc1 = 0.f, acc2 = 0.f, acc3 = 0.f;

    for (int j0 = 0; j0 < TT; j0 += 32) {
        {
            int r  = tid >> 3;
            int cb = (tid & 7) * 4;
            int i  = it * 32 + r;
            #pragma unroll
            for (int u = 0; u < 4; u++) {
                int j = j0 + cb + u;
                As[r][cb + u] = (i < TT && j < TT) ? att[((size_t)bh * TT + i) * TT + j] : 0.f;
            }
            int jr = j0 + r;
            float4 vv = make_float4(0.f, 0.f, 0.f, 0.f);
            if (jr < TT)
                vv = *(const float4*)&v[(((size_t)b * TT + jr) * NHH + h) * HDD + dt * 32 + cb];
            Vs[r][cb+0]=vv.x; Vs[r][cb+1]=vv.y; Vs[r][cb+2]=vv.z; Vs[r][cb+3]=vv.w;
        }
        __syncthreads();
        #pragma unroll
        for (int jj = 0; jj < 32; jj++) {
            float a = As[il][jj];
            acc0 = fmaf(a, Vs[jj][db + 0], acc0);
            acc1 = fmaf(a, Vs[jj][db + 1], acc1);
            acc2 = fmaf(a, Vs[jj][db + 2], acc2);
            acc3 = fmaf(a, Vs[jj][db + 3], acc3);
        }
        __syncthreads();
    }
    int i = it * 32 + il;
    if (i < TT) {
        size_t base = (((size_t)b * TT + i) * NHH + h) * HDD + dt * 32 + db;
        float4 o = make_float4(acc0, acc1, acc2, acc3);
        *(float4*)&y[base] = o;
    }
}

// ---------------- host orchestration ----------------
extern "C" void kernel_launch(void* const* d_in, const int* in_sizes, int n_in,
                              void* d_out, int out_size)
{
    const float* tok_emb = (const float*)d_in[0];
    const float* cls_emb = (const float*)d_in[1];
    const float* pos_emb = (const float*)d_in[2];
    const float* ln1_w   = (const float*)d_in[3];
    const float* ln1_b   = (const float*)d_in[4];
    const float* Wq      = (const float*)d_in[5];
    const float* bq      = (const float*)d_in[6];
    const float* Wk      = (const float*)d_in[7];
    const float* bk      = (const float*)d_in[8];
    const float* Wv      = (const float*)d_in[9];
    const float* bv      = (const float*)d_in[10];
    const float* Wo      = (const float*)d_in[11];
    const float* bo      = (const float*)d_in[12];
    const float* ln2_w   = (const float*)d_in[13];
    const float* ln2_b   = (const float*)d_in[14];
    const float* W1      = (const float*)d_in[15];
    const float* b1      = (const float*)d_in[16];
    const float* W2      = (const float*)d_in[17];
    const float* b2      = (const float*)d_in[18];
    const float* lnf_w   = (const float*)d_in[19];
    const float* lnf_b   = (const float*)d_in[20];
    const int* idx_tok   = (const int*)d_in[21];
    const int* idx_cls   = (const int*)d_in[22];
    float* out = (float*)d_out;

    float *X, *H, *Q, *K, *V, *Y, *ATT, *MLP;
    cudaGetSymbolAddress((void**)&X,   g_x);
    cudaGetSymbolAddress((void**)&H,   g_h);
    cudaGetSymbolAddress((void**)&Q,   g_q);
    cudaGetSymbolAddress((void**)&K,   g_k);
    cudaGetSymbolAddress((void**)&V,   g_v);
    cudaGetSymbolAddress((void**)&Y,   g_y);
    cudaGetSymbolAddress((void**)&ATT, g_att);
    cudaGetSymbolAddress((void**)&MLP, g_mlp);

    embed_kernel<<<MM, 256>>>(tok_emb, cls_emb, pos_emb, idx_tok, idx_cls, X);

    dim3 gridProj(CC / 128, (MM + 127) / 128);         // 8  x 65
    dim3 gridMlp1(C4 / 128, (MM + 127) / 128);         // 32 x 65
    dim3 gridMlp2(CC / 128, (MM + 127) / 128);
    dim3 gridLogit(VV / 128, (MM + 127) / 128);        // 128 x 65
    dim3 gridScore(9, 9, BB * NHH);
    dim3 gridAV(9, 2, BB * NHH);
    int smRows = (BB * NHH * TT + 3) / 4;

    for (int l = 0; l < LL; l++) {
        const float* l1w = ln1_w + (size_t)l * CC;
        const float* l1b = ln1_b + (size_t)l * CC;
        const float* wq  = Wq + (size_t)l * CC * CC;
        const float* wk  = Wk + (size_t)l * CC * CC;
        const float* wv  = Wv + (size_t)l * CC * CC;
        const float* wo  = Wo + (size_t)l * CC * CC;
        const float* bql = bq + (size_t)l * CC;
        const float* bkl = bk + (size_t)l * CC;
        const float* bvl = bv + (size_t)l * CC;
        const float* bol = bo + (size_t)l * CC;
        const float* l2w = ln2_w + (size_t)l * CC;
        const float* l2b = ln2_b + (size_t)l * CC;
        const float* w1  = W1 + (size_t)l * C4 * CC;
        const float* b1l = b1 + (size_t)l * C4;
        const float* w2  = W2 + (size_t)l * CC * C4;
        const float* b2l = b2 + (size_t)l * CC;

        layernorm_kernel<<<MM, 256>>>(X, l1w, l1b, H);

        tgemm_nt<false, false><<<gridProj, 256>>>(H, wq, bql, nullptr, Q, MM, CC, CC);
        tgemm_nt<false, false><<<gridProj, 256>>>(H, wk, bkl, nullptr, K, MM, CC, CC);
        tgemm_nt<false, false><<<gridProj, 256>>>(H, wv, bvl, nullptr, V, MM, CC, CC);

        attn_scores_kernel<<<gridScore, 256>>>(Q, K, ATT);
        softmax_kernel<<<smRows, 128>>>(ATT);
        attn_av_kernel<<<gridAV, 256>>>(ATT, V, Y);

        // x = x + y @ Wo^T + bo
        tgemm_nt<true, false><<<gridProj, 256>>>(Y, wo, bol, X, X, MM, CC, CC);

        layernorm_kernel<<<MM, 256>>>(X, l2w, l2b, H);
        // mlp hidden = gelu(h @ W1^T + b1)
        tgemm_nt<false, true><<<gridMlp1, 256>>>(H, w1, b1l, nullptr, MLP, MM, C4, CC);
        // x = x + mlp @ W2^T + b2
        tgemm_nt<true, false><<<gridMlp2, 256>>>(MLP, w2, b2l, X, X, MM, CC, C4);
    }

    layernorm_kernel<<<MM, 256>>>(X, lnf_w, lnf_b, H);
    // logits = h @ tok_emb^T
    tgemm_nt<false, false><<<gridLogit, 256>>>(H, tok_emb, nullptr, nullptr, out, MM, VV, CC);
}

// round 6
// speedup vs baseline: 2.2023x; 1.1007x over previous
#include <cuda_runtime.h>
#include <math.h>
#include <stdint.h>

// ---------------- problem constants ----------------
#define BB    32
#define TTOK  256
#define TT    257          // T_TOK + 1 (class token)
#define CC    1024
#define NHH   16
#define HDD   64
#define LL    12
#define VV    16384
#define MM    (BB * TT)    // 8224 rows
#define C4    (4 * CC)     // 4096
#define LN_EPS 1e-5f
#define ATT_SCALE 0.125f   // 1/sqrt(64)

// ---------------- scratch (device globals; no allocation allowed) ----------------
__device__ float g_x  [(size_t)MM * CC];
__device__ float g_h  [(size_t)MM * CC];
__device__ float g_q  [(size_t)MM * CC];
__device__ float g_k  [(size_t)MM * CC];
__device__ float g_v  [(size_t)MM * CC];
__device__ float g_y  [(size_t)MM * CC];
__device__ float g_att[(size_t)BB * NHH * TT * TT];
__device__ float g_mlp[(size_t)MM * C4];

// ---------------- tf32 helpers ----------------
__device__ __forceinline__ uint32_t f2tf32(float f) {
    uint32_t u;
    asm("cvt.rna.tf32.f32 %0, %1;" : "=r"(u) : "f"(f));
    return u;
}

__device__ __forceinline__ void mma_tf32(float* c, const uint32_t* a,
                                         uint32_t b0, uint32_t b1) {
    asm volatile(
        "mma.sync.aligned.m16n8k8.row.col.f32.tf32.tf32.f32 "
        "{%0,%1,%2,%3}, {%4,%5,%6,%7}, {%8,%9}, {%0,%1,%2,%3};\n"
        : "+f"(c[0]), "+f"(c[1]), "+f"(c[2]), "+f"(c[3])
        : "r"(a[0]), "r"(a[1]), "r"(a[2]), "r"(a[3]), "r"(b0), "r"(b1));
}

// ---------------- embedding ----------------
__global__ void __launch_bounds__(256) embed_kernel(
    const float* __restrict__ tok_emb, const float* __restrict__ cls_emb,
    const float* __restrict__ pos_emb, const int* __restrict__ idx_tok,
    const int* __restrict__ idx_cls, float* __restrict__ x)
{
    int bt = blockIdx.x;
    int b = bt / TT, t = bt % TT;
    const float* src;
    if (t == 0) src = cls_emb + (size_t)idx_cls[b] * CC;
    else        src = tok_emb + (size_t)idx_tok[b * TTOK + (t - 1)] * CC;
    const float4* s4 = (const float4*)src;
    const float4* p4 = (const float4*)(pos_emb + (size_t)t * CC);
    float4*       o4 = (float4*)(x + (size_t)bt * CC);
    int tid = threadIdx.x;
    float4 a = s4[tid], p = p4[tid];
    a.x += p.x; a.y += p.y; a.z += p.z; a.w += p.w;
    o4[tid] = a;
}

// ---------------- LayerNorm ----------------
__global__ void __launch_bounds__(256) layernorm_kernel(
    const float* __restrict__ x, const float* __restrict__ w,
    const float* __restrict__ b, float* __restrict__ out)
{
    int row = blockIdx.x;
    int tid = threadIdx.x;
    const float4* x4 = (const float4*)(x + (size_t)row * CC);
    float4 v = x4[tid];
    float s  = v.x + v.y + v.z + v.w;
    float ss = v.x * v.x + v.y * v.y + v.z * v.z + v.w * v.w;
    #pragma unroll
    for (int o = 16; o > 0; o >>= 1) {
        s  += __shfl_xor_sync(0xffffffffu, s,  o);
        ss += __shfl_xor_sync(0xffffffffu, ss, o);
    }
    __shared__ float rs[8], rss[8], bc[2];
    int wid = tid >> 5, lane = tid & 31;
    if (lane == 0) { rs[wid] = s; rss[wid] = ss; }
    __syncthreads();
    if (wid == 0) {
        float a  = (lane < 8) ? rs[lane]  : 0.f;
        float a2 = (lane < 8) ? rss[lane] : 0.f;
        #pragma unroll
        for (int o = 4; o > 0; o >>= 1) {
            a  += __shfl_xor_sync(0xffffffffu, a,  o);
            a2 += __shfl_xor_sync(0xffffffffu, a2, o);
        }
        if (lane == 0) { bc[0] = a; bc[1] = a2; }
    }
    __syncthreads();
    float mean = bc[0] * (1.0f / CC);
    float var  = bc[1] * (1.0f / CC) - mean * mean;
    float inv  = rsqrtf(var + LN_EPS);
    const float4* w4 = (const float4*)w;
    const float4* b4 = (const float4*)b;
    float4 wv = w4[tid], bv = b4[tid], o;
    o.x = (v.x - mean) * inv * wv.x + bv.x;
    o.y = (v.y - mean) * inv * wv.y + bv.y;
    o.z = (v.z - mean) * inv * wv.z + bv.z;
    o.w = (v.w - mean) * inv * wv.w + bv.w;
    ((float4*)(out + (size_t)row * CC))[tid] = o;
}

// ---------------- TF32 tensor-core GEMM, fragment-major SMEM ----------------
// C = epi(A @ W^T + bias). A: MxK fp32 row-major, W: NxK fp32 row-major.
// Block 128x128, BK=16, 8 warps (4m x 2n), warp tile 32x64.
// SMEM holds tf32 fragments in MMA layout:
//   A region ((slice*2+ks)*2+subm)*128 words; element (r16,k8) at
//     chunk = ((r16&7)*4 + (k8&3)) ^ (((r16&7)*4+(k8&3))>>3), word = chunk*4 + (r16>>3) + 2*(k8>>2)
//   B region (p*2+ks)*128 words; element (col,k8) at
//     chunk = ((col&7)*4 + (k8&3)) ^ (..>>3), word = chunk*4 + ((col>>3)&1)*2 + (k8>>2)
// Consumer: LDS.128 at chunk' = lane ^ (lane>>3) — conflict-free.
template <bool RES, bool GELU_>
__global__ void __launch_bounds__(256, 2) tgemm_nt(
    const float* __restrict__ A, const float* __restrict__ W,
    const float* __restrict__ bias, const float* __restrict__ res,
    float* __restrict__ C, int M, int N, int K)
{
    __shared__ uint32_t As[2][2048];
    __shared__ uint32_t Bs[2][2048];

    int bm = blockIdx.y * 128;
    int bn = blockIdx.x * 128;
    int tid = threadIdx.x;
    int lane = tid & 31;
    int wid  = tid >> 5;
    int g  = lane >> 2;
    int t4 = lane & 3;
    int wm = (wid & 3) * 32;
    int wn = (wid >> 2) * 64;

    // loader mapping
    int lrow = tid >> 1;           // 0..127
    int lks  = tid & 1;            // which 8-k half of the 16-k slab
    const float* Arow = A + (size_t)(bm + lrow) * K;
    const float* Wrow = W + (size_t)(bn + lrow) * K;
    bool a_ok = (bm + lrow) < M;

    // loader precomputed fragment-address constants
    int a_region = (((lrow >> 5) * 2 + lks) * 2 + ((lrow >> 4) & 1)) * 128;
    int a_laneB  = (lrow & 7) * 4;
    int a_c      = (lrow & 7) >> 1;
    int a_r0     = (lrow >> 3) & 1;
    int b_region = ((lrow >> 4) * 2 + lks) * 128;
    int b_laneB  = a_laneB;        // (lrow&7)*4
    int b_c      = a_c;
    int b_r0     = ((lrow >> 3) & 1) * 2;

    // consumer constants
    int chunkOff = (lane ^ (lane >> 3)) * 4;
    int aRegBase = (wid & 3) * 512;           // slice*2*2*128
    int bRegBase = (wid >> 2) * 4 * 256;      // p start * 2 * 128

    float acc[2][8][4];
    #pragma unroll
    for (int im = 0; im < 2; im++)
        #pragma unroll
        for (int in_ = 0; in_ < 8; in_++)
            #pragma unroll
            for (int r = 0; r < 4; r++) acc[im][in_][r] = 0.f;

    // helper macro: scatter one 8-k run of A into fragment layout
#define STORE_A(buf_, v0, v1) {                                              \
        float _q0[4] = {(v0).x,(v0).y,(v0).z,(v0).w};                        \
        float _q1[4] = {(v1).x,(v1).y,(v1).z,(v1).w};                        \
        _Pragma("unroll")                                                    \
        for (int _t = 0; _t < 4; _t++) {                                     \
            int _ch = (a_laneB + _t) ^ a_c;                                  \
            As[buf_][a_region + _ch*4 + a_r0]     = f2tf32(_q0[_t]);         \
            As[buf_][a_region + _ch*4 + a_r0 + 2] = f2tf32(_q1[_t]);         \
        } }
#define STORE_B(buf_, v0, v1) {                                              \
        float _q0[4] = {(v0).x,(v0).y,(v0).z,(v0).w};                        \
        float _q1[4] = {(v1).x,(v1).y,(v1).z,(v1).w};                        \
        _Pragma("unroll")                                                    \
        for (int _t = 0; _t < 4; _t++) {                                     \
            int _ch = (b_laneB + _t) ^ b_c;                                  \
            Bs[buf_][b_region + _ch*4 + b_r0]     = f2tf32(_q0[_t]);         \
            Bs[buf_][b_region + _ch*4 + b_r0 + 1] = f2tf32(_q1[_t]);         \
        } }

    // ---- preload tile 0 ----
    {
        int kbase = lks * 8;
        float4 a0 = make_float4(0.f,0.f,0.f,0.f), a1 = a0;
        if (a_ok) {
            a0 = *(const float4*)&Arow[kbase];
            a1 = *(const float4*)&Arow[kbase + 4];
        }
        float4 w0 = *(const float4*)&Wrow[kbase];
        float4 w1 = *(const float4*)&Wrow[kbase + 4];
        STORE_A(0, a0, a1);
        STORE_B(0, w0, w1);
    }
    __syncthreads();

    int buf = 0;
    for (int k0 = 0; k0 < K; k0 += 16) {
        // register prefetch of next K-slab
        float4 pa0, pa1, pw0, pw1;
        bool has_next = (k0 + 16 < K);
        if (has_next) {
            int kn = k0 + 16 + lks * 8;
            pa0 = make_float4(0.f,0.f,0.f,0.f); pa1 = pa0;
            if (a_ok) {
                pa0 = *(const float4*)&Arow[kn];
                pa1 = *(const float4*)&Arow[kn + 4];
            }
            pw0 = *(const float4*)&Wrow[kn];
            pw1 = *(const float4*)&Wrow[kn + 4];
        }

        // ---- compute: 2 k-steps of 8 ----
        #pragma unroll
        for (int ks = 0; ks < 2; ks++) {
            uint4 afv[2];
            #pragma unroll
            for (int subm = 0; subm < 2; subm++)
                afv[subm] = *(const uint4*)&As[buf][aRegBase + (ks*2 + subm)*128 + chunkOff];
            uint4 bfv[4];
            #pragma unroll
            for (int pl = 0; pl < 4; pl++)
                bfv[pl] = *(const uint4*)&Bs[buf][bRegBase + (pl*2 + ks)*128 + chunkOff];

            #pragma unroll
            for (int pl = 0; pl < 4; pl++) {
                mma_tf32(acc[0][2*pl+0], (const uint32_t*)&afv[0], bfv[pl].x, bfv[pl].y);
                mma_tf32(acc[1][2*pl+0], (const uint32_t*)&afv[1], bfv[pl].x, bfv[pl].y);
                mma_tf32(acc[0][2*pl+1], (const uint32_t*)&afv[0], bfv[pl].z, bfv[pl].w);
                mma_tf32(acc[1][2*pl+1], (const uint32_t*)&afv[1], bfv[pl].z, bfv[pl].w);
            }
        }

        if (has_next) {
            int nb = buf ^ 1;
            STORE_A(nb, pa0, pa1);
            STORE_B(nb, pw0, pw1);
            __syncthreads();
            buf = nb;
        }
    }
#undef STORE_A
#undef STORE_B

    // ---- epilogue ----
    #pragma unroll
    for (int im = 0; im < 2; im++) {
        int r0 = bm + wm + im * 16 + g;
        #pragma unroll
        for (int in_ = 0; in_ < 8; in_++) {
            int col = bn + wn + in_ * 8 + t4 * 2;
            float bx = 0.f, by = 0.f;
            if (bias) { bx = bias[col]; by = bias[col + 1]; }
            #pragma unroll
            for (int half = 0; half < 2; half++) {
                int row = r0 + half * 8;
                if (row >= M) continue;
                float vx = acc[im][in_][half * 2 + 0] + bx;
                float vy = acc[im][in_][half * 2 + 1] + by;
                if (GELU_) {
                    vx = 0.5f * vx * (1.f + erff(vx * 0.70710678118f));
                    vy = 0.5f * vy * (1.f + erff(vy * 0.70710678118f));
                }
                if (RES) {
                    float2 rv = *(const float2*)&res[(size_t)row * N + col];
                    vx += rv.x; vy += rv.y;
                }
                float2 o = make_float2(vx, vy);
                *(float2*)&C[(size_t)row * N + col] = o;
            }
        }
    }
}

// ---------------- attention scores (fp32) ----------------
__global__ void __launch_bounds__(256) attn_scores_kernel(
    const float* __restrict__ q, const float* __restrict__ k, float* __restrict__ att)
{
    int jt = blockIdx.x, it = blockIdx.y;
    if (jt > it) return;
    int bh = blockIdx.z;
    int b = bh / NHH, h = bh % NHH;
    __shared__ float Qs[32][65];
    __shared__ float Ks[32][65];
    int tid = threadIdx.x;

    #pragma unroll
    for (int rep = 0; rep < 2; rep++) {
        int f = tid + rep * 256;
        int row = f >> 4;
        int c4  = (f & 15) * 4;
        {
            int i = it * 32 + row;
            float4 v = make_float4(0.f, 0.f, 0.f, 0.f);
            if (i < TT) v = *(const float4*)&q[(((size_t)b * TT + i) * NHH + h) * HDD + c4];
            Qs[row][c4+0]=v.x; Qs[row][c4+1]=v.y; Qs[row][c4+2]=v.z; Qs[row][c4+3]=v.w;
        }
        {
            int j = jt * 32 + row;
            float4 v = make_float4(0.f, 0.f, 0.f, 0.f);
            if (j < TT) v = *(const float4*)&k[(((size_t)b * TT + j) * NHH + h) * HDD + c4];
            Ks[row][c4+0]=v.x; Ks[row][c4+1]=v.y; Ks[row][c4+2]=v.z; Ks[row][c4+3]=v.w;
        }
    }
    __syncthreads();

    int il = tid >> 3;
    int jb = (tid & 7) * 4;
    float a0 = 0.f, a1 = 0.f, a2 = 0.f, a3 = 0.f;
    #pragma unroll
    for (int kk = 0; kk < 64; kk++) {
        float qv = Qs[il][kk];
        a0 = fmaf(qv, Ks[jb + 0][kk], a0);
        a1 = fmaf(qv, Ks[jb + 1][kk], a1);
        a2 = fmaf(qv, Ks[jb + 2][kk], a2);
        a3 = fmaf(qv, Ks[jb + 3][kk], a3);
    }
    int i = it * 32 + il;
    if (i < TT) {
        size_t base = ((size_t)bh * TT + i) * TT;
        float r[4] = {a0, a1, a2, a3};
        #pragma unroll
        for (int u = 0; u < 4; u++) {
            int j = jt * 32 + jb + u;
            if (j < TT && j <= i) att[base + j] = r[u] * ATT_SCALE;
        }
    }
}

// ---------------- causal softmax ----------------
__global__ void __launch_bounds__(128) softmax_kernel(float* __restrict__ att)
{
    int row = blockIdx.x * 4 + (threadIdx.x >> 5);
    if (row >= BB * NHH * TT) return;
    int lane = threadIdx.x & 31;
    int i = row % TT;
    float* p = att + (size_t)row * TT;
    int len = i + 1;
    float m = -3.4e38f;
    for (int j = lane; j < len; j += 32) m = fmaxf(m, p[j]);
    #pragma unroll
    for (int o = 16; o > 0; o >>= 1) m = fmaxf(m, __shfl_xor_sync(0xffffffffu, m, o));
    float s = 0.f;
    for (int j = lane; j < len; j += 32) { float e = expf(p[j] - m); p[j] = e; s += e; }
    #pragma unroll
    for (int o = 16; o > 0; o >>= 1) s += __shfl_xor_sync(0xffffffffu, s, o);
    float inv = 1.f / s;
    for (int j = lane; j < TT; j += 32) p[j] = (j < len) ? p[j] * inv : 0.f;
}

// ---------------- AV (fp32) ----------------
__global__ void __launch_bounds__(256) attn_av_kernel(
    const float* __restrict__ att, const float* __restrict__ v, float* __restrict__ y)
{
    int it = blockIdx.x, dt = blockIdx.y, bh = blockIdx.z;
    int b = bh / NHH, h = bh % NHH;
    __shared__ float As[32][33];
    __shared__ float Vs[32][33];
    int tid = threadIdx.x;
    int il = tid >> 3;
    int db = (tid & 7) * 4;
    float acc0 = 0.f, acc1 = 0.f, acc2 = 0.f, acc3 = 0.f;

    for (int j0 = 0; j0 < TT; j0 += 32) {
        {
            int r  = tid >> 3;
            int cb = (tid & 7) * 4;
            int i  = it * 32 + r;
            #pragma unroll
            for (int u = 0; u < 4; u++) {
                int j = j0 + cb + u;
                As[r][cb + u] = (i < TT && j < TT) ? att[((size_t)bh * TT + i) * TT + j] : 0.f;
            }
            int jr = j0 + r;
            float4 vv = make_float4(0.f, 0.f, 0.f, 0.f);
            if (jr < TT)
                vv = *(const float4*)&v[(((size_t)b * TT + jr) * NHH + h) * HDD + dt * 32 + cb];
            Vs[r][cb+0]=vv.x; Vs[r][cb+1]=vv.y; Vs[r][cb+2]=vv.z; Vs[r][cb+3]=vv.w;
        }
        __syncthreads();
        #pragma unroll
        for (int jj = 0; jj < 32; jj++) {
            float a = As[il][jj];
            acc0 = fmaf(a, Vs[jj][db + 0], acc0);
            acc1 = fmaf(a, Vs[jj][db + 1], acc1);
            acc2 = fmaf(a, Vs[jj][db + 2], acc2);
            acc3 = fmaf(a, Vs[jj][db + 3], acc3);
        }
        __syncthreads();
    }
    int i = it * 32 + il;
    if (i < TT) {
        size_t base = (((size_t)b * TT + i) * NHH + h) * HDD + dt * 32 + db;
        float4 o = make_float4(acc0, acc1, acc2, acc3);
        *(float4*)&y[base] = o;
    }
}

// ---------------- host orchestration ----------------
extern "C" void kernel_launch(void* const* d_in, const int* in_sizes, int n_in,
                              void* d_out, int out_size)
{
    const float* tok_emb = (const float*)d_in[0];
    const float* cls_emb = (const float*)d_in[1];
    const float* pos_emb = (const float*)d_in[2];
    const float* ln1_w   = (const float*)d_in[3];
    const float* ln1_b   = (const float*)d_in[4];
    const float* Wq      = (const float*)d_in[5];
    const float* bq      = (const float*)d_in[6];
    const float* Wk      = (const float*)d_in[7];
    const float* bk      = (const float*)d_in[8];
    const float* Wv      = (const float*)d_in[9];
    const float* bv      = (const float*)d_in[10];
    const float* Wo      = (const float*)d_in[11];
    const float* bo      = (const float*)d_in[12];
    const float* ln2_w   = (const float*)d_in[13];
    const float* ln2_b   = (const float*)d_in[14];
    const float* W1      = (const float*)d_in[15];
    const float* b1      = (const float*)d_in[16];
    const float* W2      = (const float*)d_in[17];
    const float* b2      = (const float*)d_in[18];
    const float* lnf_w   = (const float*)d_in[19];
    const float* lnf_b   = (const float*)d_in[20];
    const int* idx_tok   = (const int*)d_in[21];
    const int* idx_cls   = (const int*)d_in[22];
    float* out = (float*)d_out;

    float *X, *H, *Q, *K, *V, *Y, *ATT, *MLP;
    cudaGetSymbolAddress((void**)&X,   g_x);
    cudaGetSymbolAddress((void**)&H,   g_h);
    cudaGetSymbolAddress((void**)&Q,   g_q);
    cudaGetSymbolAddress((void**)&K,   g_k);
    cudaGetSymbolAddress((void**)&V,   g_v);
    cudaGetSymbolAddress((void**)&Y,   g_y);
    cudaGetSymbolAddress((void**)&ATT, g_att);
    cudaGetSymbolAddress((void**)&MLP, g_mlp);

    embed_kernel<<<MM, 256>>>(tok_emb, cls_emb, pos_emb, idx_tok, idx_cls, X);

    dim3 gridProj(CC / 128, (MM + 127) / 128);
    dim3 gridMlp1(C4 / 128, (MM + 127) / 128);
    dim3 gridMlp2(CC / 128, (MM + 127) / 128);
    dim3 gridLogit(VV / 128, (MM + 127) / 128);
    dim3 gridScore(9, 9, BB * NHH);
    dim3 gridAV(9, 2, BB * NHH);
    int smRows = (BB * NHH * TT + 3) / 4;

    for (int l = 0; l < LL; l++) {
        const float* l1w = ln1_w + (size_t)l * CC;
        const float* l1b = ln1_b + (size_t)l * CC;
        const float* wq  = Wq + (size_t)l * CC * CC;
        const float* wk  = Wk + (size_t)l * CC * CC;
        const float* wv  = Wv + (size_t)l * CC * CC;
        const float* wo  = Wo + (size_t)l * CC * CC;
        const float* bql = bq + (size_t)l * CC;
        const float* bkl = bk + (size_t)l * CC;
        const float* bvl = bv + (size_t)l * CC;
        const float* bol = bo + (size_t)l * CC;
        const float* l2w = ln2_w + (size_t)l * CC;
        const float* l2b = ln2_b + (size_t)l * CC;
        const float* w1  = W1 + (size_t)l * C4 * CC;
        const float* b1l = b1 + (size_t)l * C4;
        const float* w2  = W2 + (size_t)l * CC * C4;
        const float* b2l = b2 + (size_t)l * CC;

        layernorm_kernel<<<MM, 256>>>(X, l1w, l1b, H);

        tgemm_nt<false, false><<<gridProj, 256>>>(H, wq, bql, nullptr, Q, MM, CC, CC);
        tgemm_nt<false, false><<<gridProj, 256>>>(H, wk, bkl, nullptr, K, MM, CC, CC);
        tgemm_nt<false, false><<<gridProj, 256>>>(H, wv, bvl, nullptr, V, MM, CC, CC);

        attn_scores_kernel<<<gridScore, 256>>>(Q, K, ATT);
        softmax_kernel<<<smRows, 128>>>(ATT);
        attn_av_kernel<<<gridAV, 256>>>(ATT, V, Y);

        tgemm_nt<true, false><<<gridProj, 256>>>(Y, wo, bol, X, X, MM, CC, CC);

        layernorm_kernel<<<MM, 256>>>(X, l2w, l2b, H);
        tgemm_nt<false, true><<<gridMlp1, 256>>>(H, w1, b1l, nullptr, MLP, MM, C4, CC);
        tgemm_nt<true, false><<<gridMlp2, 256>>>(MLP, w2, b2l, X, X, MM, CC, C4);
    }

    layernorm_kernel<<<MM, 256>>>(X, lnf_w, lnf_b, H);
    tgemm_nt<false, false><<<gridLogit, 256>>>(H, tok_emb, nullptr, nullptr, out, MM, VV, CC);
}